// round 8
// baseline (speedup 1.0000x reference)
#include <cuda_runtime.h>
#include <cuda_fp16.h>
#include <math.h>

// ---------------- problem constants ----------------
#define MAX_NODES 50000
#define MAX_EDGES 600000
#define IN_CH 768
#define HID 128
#define REL_DIM 200
#define NUM_RELS 5

// ---------------- scratch (device globals) ----------------
__device__ float g_h[MAX_NODES * HID];
__device__ float g_wx[MAX_NODES * HID];
__device__ float g_agg[MAX_NODES * HID];
__device__ float g_sA[MAX_NODES];
__device__ float g_sB[MAX_NODES];
__device__ float g_relC[8];
__device__ int g_cnt[MAX_NODES];
__device__ int g_off[MAX_NODES + 1];
__device__ int g_cur[MAX_NODES];
__device__ int g_csr_src[MAX_EDGES];
__device__ int g_csr_et[MAX_EDGES];

static inline int cdiv(int a, int b) { return (a + b - 1) / b; }

__device__ __forceinline__ unsigned hpack(__half a, __half b) {
    unsigned short ua = *(unsigned short*)&a;
    unsigned short ub = *(unsigned short*)&b;
    return (unsigned)ua | ((unsigned)ub << 16);
}
__device__ __forceinline__ unsigned cvt2h(float x, float y) {
    return hpack(__float2half_rn(x), __float2half_rn(y));
}
__device__ __forceinline__ void split2h(float x, float y, unsigned& hi, unsigned& lo) {
    __half h0 = __float2half_rn(x), h1 = __float2half_rn(y);
    __half l0 = __float2half_rn(x - __half2float(h0));
    __half l1 = __float2half_rn(y - __half2float(h1));
    hi = hpack(h0, h1);
    lo = hpack(l0, l1);
}

// ---------------- HMMA fp16 GEMM (pipelined + ldmatrix) ----------------
// C[M,128] = A[M,K] @ B[128,K]^T. A rounded to fp16; B split hi/lo.
// C = A16*Bhi + A16*Blo. err ~2^-12 rel. CTA 128x128, BK=32, 8 warps (2x4).
#define F_BIASLEAKY 1
#define F_ROWDOT 2
#define GPAD 40

__device__ __forceinline__ void hmma16816(float* c, const unsigned* a, const unsigned* b) {
    asm volatile(
        "mma.sync.aligned.m16n8k16.row.col.f32.f16.f16.f32 "
        "{%0,%1,%2,%3}, {%4,%5,%6,%7}, {%8,%9}, {%0,%1,%2,%3};"
        : "+f"(c[0]), "+f"(c[1]), "+f"(c[2]), "+f"(c[3])
        : "r"(a[0]), "r"(a[1]), "r"(a[2]), "r"(a[3]), "r"(b[0]), "r"(b[1]));
}
__device__ __forceinline__ void ldmatrix_x4(unsigned& r0, unsigned& r1, unsigned& r2,
                                            unsigned& r3, unsigned addr) {
    asm volatile("ldmatrix.sync.aligned.m8n8.x4.shared.b16 {%0,%1,%2,%3}, [%4];"
                 : "=r"(r0), "=r"(r1), "=r"(r2), "=r"(r3)
                 : "r"(addr));
}
__device__ __forceinline__ unsigned smem_u32(const void* p) {
    return (unsigned)__cvta_generic_to_shared(p);
}

__global__ __launch_bounds__(256, 2) void gemm_mma(
    const float* __restrict__ A, const float* __restrict__ B0,
    const float* __restrict__ bias, float* __restrict__ C0,
    const float* __restrict__ B1, float* __restrict__ C1,
    const float* __restrict__ avec, float* __restrict__ sA, float* __restrict__ sB,
    int M, int K, int flags0) {
    __shared__ __align__(16) __half As16[128 * GPAD];
    __shared__ __align__(16) __half Bhi[128 * GPAD];
    __shared__ __align__(16) __half Blo[128 * GPAD];
    __shared__ float s_red[2][128];

    const float* B = (blockIdx.y == 0) ? B0 : B1;
    float* C = (blockIdx.y == 0) ? C0 : C1;
    const int flags = (blockIdx.y == 0) ? flags0 : 0;

    const int tid = threadIdx.x;
    const int wid = tid >> 5;
    const int lane = tid & 31;
    const int wm = wid & 1;
    const int wn = wid >> 1;
    const int m0 = blockIdx.x * 128;
    const int g = lane >> 2;
    const int tq = lane & 3;

    float acc[4][4][4];
#pragma unroll
    for (int i = 0; i < 4; i++)
#pragma unroll
        for (int j = 0; j < 4; j++)
#pragma unroll
            for (int k = 0; k < 4; k++) acc[i][j][k] = 0.f;

    // ldmatrix lane address bases (bytes), computed once.
    // A tile order for x4: T0=(m0-7,k0-7) T1=(m8-15,k0-7) T2=(m0-7,k8-15) T3=(m8-15,k8-15)
    unsigned addrA[4];
    {
        const int rowa = (lane & 7) + ((lane >> 3) & 1) * 8;  // within 16-row tile
        const int cola = (lane >> 4) * 8;                      // 0 or 8 halves
#pragma unroll
        for (int mt = 0; mt < 4; mt++) {
            const int r = wm * 64 + mt * 16 + rowa;
            addrA[mt] = smem_u32(As16) + (unsigned)((r * GPAD + cola) * 2);
        }
    }
    // B x4 covers two n-tiles: T0=(n0-7,k0-7) T1=(n0-7,k8-15) T2=(n8-15,k0-7) T3=(n8-15,k8-15)
    unsigned addrBh[2], addrBl[2];
    {
        const int rowb = (lane & 7) + (lane >> 4) * 8;
        const int colb = ((lane >> 3) & 1) * 8;
#pragma unroll
        for (int p = 0; p < 2; p++) {
            const int r = wn * 32 + p * 16 + rowb;
            addrBh[p] = smem_u32(Bhi) + (unsigned)((r * GPAD + colb) * 2);
            addrBl[p] = smem_u32(Blo) + (unsigned)((r * GPAD + colb) * 2);
        }
    }

    const int lrow = tid >> 1;
    const int lc0 = (tid & 1) << 4;
    const int gr = m0 + lrow;
    const float* aprow = A + (size_t)gr * K + lc0;
    const float* bprow = B + (size_t)lrow * K + lc0;

    float4 av[4], bv[4];
#pragma unroll
    for (int q = 0; q < 4; q++) {
        av[q] = (gr < M) ? reinterpret_cast<const float4*>(aprow)[q]
                         : make_float4(0.f, 0.f, 0.f, 0.f);
        bv[q] = reinterpret_cast<const float4*>(bprow)[q];
    }

    const int nk = K >> 5;
    for (int it = 0; it < nk; it++) {
        __syncthreads();
        {
            unsigned ah[8];
#pragma unroll
            for (int q = 0; q < 4; q++) {
                ah[q * 2] = cvt2h(av[q].x, av[q].y);
                ah[q * 2 + 1] = cvt2h(av[q].z, av[q].w);
            }
            uint4* pa = reinterpret_cast<uint4*>(As16 + lrow * GPAD + lc0);
            pa[0] = make_uint4(ah[0], ah[1], ah[2], ah[3]);
            pa[1] = make_uint4(ah[4], ah[5], ah[6], ah[7]);
            unsigned h[8], l[8];
#pragma unroll
            for (int q = 0; q < 4; q++) {
                split2h(bv[q].x, bv[q].y, h[q * 2], l[q * 2]);
                split2h(bv[q].z, bv[q].w, h[q * 2 + 1], l[q * 2 + 1]);
            }
            uint4* qh = reinterpret_cast<uint4*>(Bhi + lrow * GPAD + lc0);
            uint4* ql = reinterpret_cast<uint4*>(Blo + lrow * GPAD + lc0);
            qh[0] = make_uint4(h[0], h[1], h[2], h[3]);
            qh[1] = make_uint4(h[4], h[5], h[6], h[7]);
            ql[0] = make_uint4(l[0], l[1], l[2], l[3]);
            ql[1] = make_uint4(l[4], l[5], l[6], l[7]);
        }
        __syncthreads();
        if (it + 1 < nk) {
            const float* ap = aprow + (it + 1) * 32;
            const float* bp = bprow + (it + 1) * 32;
#pragma unroll
            for (int q = 0; q < 4; q++) {
                av[q] = (gr < M) ? reinterpret_cast<const float4*>(ap)[q]
                                 : make_float4(0.f, 0.f, 0.f, 0.f);
                bv[q] = reinterpret_cast<const float4*>(bp)[q];
            }
        }
#pragma unroll
        for (int ks = 0; ks < 2; ks++) {
            const unsigned koff = (unsigned)(ks * 32);  // 16 halves
            unsigned a[4][4], b0[4][2], b1[4][2];
#pragma unroll
            for (int mt = 0; mt < 4; mt++)
                ldmatrix_x4(a[mt][0], a[mt][1], a[mt][2], a[mt][3], addrA[mt] + koff);
#pragma unroll
            for (int p = 0; p < 2; p++) {
                ldmatrix_x4(b0[p * 2][0], b0[p * 2][1], b0[p * 2 + 1][0], b0[p * 2 + 1][1],
                            addrBh[p] + koff);
                ldmatrix_x4(b1[p * 2][0], b1[p * 2][1], b1[p * 2 + 1][0], b1[p * 2 + 1][1],
                            addrBl[p] + koff);
            }
#pragma unroll
            for (int mt = 0; mt < 4; mt++)
#pragma unroll
                for (int nt = 0; nt < 4; nt++) hmma16816(acc[mt][nt], a[mt], b0[nt]);
#pragma unroll
            for (int mt = 0; mt < 4; mt++)
#pragma unroll
                for (int nt = 0; nt < 4; nt++) hmma16816(acc[mt][nt], a[mt], b1[nt]);
        }
    }

    // ---------------- epilogue ----------------
    const bool dorow = (flags & F_ROWDOT) != 0;
    if (dorow) {
        if (tid < 128) { s_red[0][tid] = 0.f; s_red[1][tid] = 0.f; }
        __syncthreads();
    }
#pragma unroll
    for (int mt = 0; mt < 4; mt++) {
        float pa[2] = {0.f, 0.f}, pb[2] = {0.f, 0.f};
#pragma unroll
        for (int nt = 0; nt < 4; nt++) {
            const int c = wn * 32 + nt * 8 + tq * 2;
            float bi0 = 0.f, bi1 = 0.f;
            if (flags & F_BIASLEAKY) { bi0 = bias[c]; bi1 = bias[c + 1]; }
            float aA0 = 0.f, aA1 = 0.f, aB0 = 0.f, aB1 = 0.f;
            if (dorow) {
                aA0 = avec[c]; aA1 = avec[c + 1];
                aB0 = avec[128 + c]; aB1 = avec[128 + c + 1];
            }
#pragma unroll
            for (int half = 0; half < 2; half++) {
                const int r = m0 + wm * 64 + mt * 16 + g + half * 8;
                float v0 = acc[mt][nt][half * 2 + 0];
                float v1 = acc[mt][nt][half * 2 + 1];
                if (flags & F_BIASLEAKY) {
                    v0 += bi0; v1 += bi1;
                    v0 = v0 > 0.f ? v0 : 0.01f * v0;
                    v1 = v1 > 0.f ? v1 : 0.01f * v1;
                }
                if (dorow) {
                    pa[half] += v0 * aA0 + v1 * aA1;
                    pb[half] += v0 * aB0 + v1 * aB1;
                }
                if (r < M)
                    *reinterpret_cast<float2*>(C + (size_t)r * 128 + c) = make_float2(v0, v1);
            }
        }
        if (dorow) {
#pragma unroll
            for (int half = 0; half < 2; half++) {
                const int lr = wm * 64 + mt * 16 + g + half * 8;
                atomicAdd(&s_red[0][lr], pa[half]);
                atomicAdd(&s_red[1][lr], pb[half]);
            }
        }
    }
    if (dorow) {
        __syncthreads();
        if (tid < 128 && m0 + tid < M) {
            sA[m0 + tid] = s_red[0][tid];
            sB[m0 + tid] = s_red[1][tid];
        }
    }
}

// ---------------- relC[r] = (rel[r] @ Wr^T) . aC ----------------
__global__ __launch_bounds__(1024) void relc_kernel(const float* __restrict__ Wr,
                                                    const float* __restrict__ a,
                                                    const float* __restrict__ rel,
                                                    float* __restrict__ relC) {
    __shared__ float part[4 * REL_DIM];
    __shared__ float v[REL_DIM];
    const int tid = threadIdx.x;
    const int t = tid & 255;
    const int p = tid >> 8;
    if (t < REL_DIM) {
        float s = 0.f;
        const int h0 = p * 32;
#pragma unroll 8
        for (int h = 0; h < 32; h++) s += a[2 * HID + h0 + h] * Wr[(size_t)(h0 + h) * REL_DIM + t];
        part[p * REL_DIM + t] = s;
    }
    __syncthreads();
    if (tid < REL_DIM)
        v[tid] = part[tid] + part[REL_DIM + tid] + part[2 * REL_DIM + tid] + part[3 * REL_DIM + tid];
    __syncthreads();
    const int r = tid >> 5;
    const int lane = tid & 31;
    if (r < NUM_RELS) {
        float s = 0.f;
        for (int k = lane; k < REL_DIM; k += 32) s += rel[r * REL_DIM + k] * v[k];
#pragma unroll
        for (int o = 16; o; o >>= 1) s += __shfl_xor_sync(0xFFFFFFFFu, s, o);
        if (lane == 0) relC[r] = s;
    }
}

// ---------------- CSR build (by dst) ----------------
__global__ void count_kernel(const int* __restrict__ dst, int* __restrict__ cnt, int E) {
    const int e = blockIdx.x * blockDim.x + threadIdx.x;
    if (e < E) atomicAdd(cnt + dst[e], 1);
}

__global__ __launch_bounds__(1024) void scan_kernel(const int* __restrict__ cnt,
                                                    int* __restrict__ off,
                                                    int* __restrict__ cur, int N, int E) {
    __shared__ int part[1024];
    const int tid = threadIdx.x;
    const int chunk = (N + 1023) >> 10;
    const int s0 = tid * chunk;
    int s = 0;
    for (int i = 0; i < chunk; i++) {
        const int idx = s0 + i;
        if (idx < N) s += cnt[idx];
    }
    part[tid] = s;
    __syncthreads();
    for (int o = 1; o < 1024; o <<= 1) {
        int t = (tid >= o) ? part[tid - o] : 0;
        __syncthreads();
        part[tid] += t;
        __syncthreads();
    }
    int run = part[tid] - s;  // exclusive base
    for (int i = 0; i < chunk; i++) {
        const int idx = s0 + i;
        if (idx < N) {
            off[idx] = run;
            cur[idx] = run;
            run += cnt[idx];
        }
    }
    if (tid == 0) off[N] = E;
}

__global__ void fill_kernel(const int* __restrict__ src, const int* __restrict__ dst,
                            const int* __restrict__ et, int* __restrict__ cur,
                            int* __restrict__ csr_src, int* __restrict__ csr_et, int E) {
    const int e = blockIdx.x * blockDim.x + threadIdx.x;
    if (e >= E) return;
    const int pos = atomicAdd(cur + dst[e], 1);
    csr_src[pos] = src[e];
    csr_et[pos] = et[e];
}

// ---------------- fused per-dst attention: softmax + aggregate + residual + elu(+norm)
__global__ void dst_fused_kernel(const float* __restrict__ wx, const float* __restrict__ res,
                                 const float* __restrict__ sA, const float* __restrict__ sB,
                                 const float* __restrict__ relC, const int* __restrict__ off,
                                 const int* __restrict__ csr_src, const int* __restrict__ csr_et,
                                 float* __restrict__ hout, int N, int fin) {
    const int d = (blockIdx.x * blockDim.x + threadIdx.x) >> 5;
    if (d >= N) return;
    const int lane = threadIdx.x & 31;
    const int rs = off[d];
    const int re = off[d + 1];
    const float sAd = sA[d];

    float4 acc = make_float4(0.f, 0.f, 0.f, 0.f);
    float psum = 0.f;
    for (int j0 = rs; j0 < re; j0 += 32) {
        const int j = j0 + lane;
        float p = 0.f;
        int s = 0;
        if (j < re) {
            s = csr_src[j];
            const int t = csr_et[j];
            float sc = sAd + sB[s] + relC[t];
            sc = sc > 0.f ? sc : 0.2f * sc;
            p = __expf(sc);
        }
        psum += p;
        const int cnt = min(32, re - j0);
        for (int k = 0; k < cnt; k++) {
            const float pk = __shfl_sync(0xFFFFFFFFu, p, k);
            const int sk = __shfl_sync(0xFFFFFFFFu, s, k);
            const float4 v = reinterpret_cast<const float4*>(wx + (size_t)sk * 128)[lane];
            acc.x += v.x * pk;
            acc.y += v.y * pk;
            acc.z += v.z * pk;
            acc.w += v.w * pk;
        }
    }
#pragma unroll
    for (int o = 16; o; o >>= 1) psum += __shfl_xor_sync(0xFFFFFFFFu, psum, o);
    const float inv = psum > 0.f ? 1.f / psum : 0.f;

    const float4 r = reinterpret_cast<const float4*>(res + (size_t)d * 128)[lane];
    float4 v;
    v.x = acc.x * inv + r.x;
    v.y = acc.y * inv + r.y;
    v.z = acc.z * inv + r.z;
    v.w = acc.w * inv + r.w;
    v.x = v.x > 0.f ? v.x : expm1f(v.x);
    v.y = v.y > 0.f ? v.y : expm1f(v.y);
    v.z = v.z > 0.f ? v.z : expm1f(v.z);
    v.w = v.w > 0.f ? v.w : expm1f(v.w);
    if (fin) {
        float ss = v.x * v.x + v.y * v.y + v.z * v.z + v.w * v.w;
#pragma unroll
        for (int o = 16; o; o >>= 1) ss += __shfl_xor_sync(0xFFFFFFFFu, ss, o);
        const float nrm = 1.f / fmaxf(sqrtf(ss), 1e-12f);
        v.x *= nrm; v.y *= nrm; v.z *= nrm; v.w *= nrm;
    }
    reinterpret_cast<float4*>(hout + (size_t)d * 128)[lane] = v;
}

// ---------------- launch ----------------
extern "C" void kernel_launch(void* const* d_in, const int* in_sizes, int n_in,
                              void* d_out, int out_size) {
    const float* x = (const float*)d_in[0];
    const int* ei = (const int*)d_in[1];
    const int* et = (const int*)d_in[2];
    const float* l1W = (const float*)d_in[3];
    const float* l1b = (const float*)d_in[4];
    const float* l2W = (const float*)d_in[5];
    const float* l2b = (const float*)d_in[6];
    const float* W1 = (const float*)d_in[7];
    const float* Wr1 = (const float*)d_in[8];
    const float* a1 = (const float*)d_in[9];
    const float* Wres1 = (const float*)d_in[10];
    const float* rel1 = (const float*)d_in[11];
    const float* W2 = (const float*)d_in[12];
    const float* Wr2 = (const float*)d_in[13];
    const float* a2 = (const float*)d_in[14];
    const float* Wres2 = (const float*)d_in[15];
    const float* rel2 = (const float*)d_in[16];

    const int N = in_sizes[0] / IN_CH;
    const int E = in_sizes[2];
    const int* src = ei;
    const int* dst = ei + E;

    float *h, *wx, *agg, *sA, *sB, *relC;
    int *cnt, *off, *cur, *csr_src, *csr_et;
    cudaGetSymbolAddress((void**)&h, g_h);
    cudaGetSymbolAddress((void**)&wx, g_wx);
    cudaGetSymbolAddress((void**)&agg, g_agg);
    cudaGetSymbolAddress((void**)&sA, g_sA);
    cudaGetSymbolAddress((void**)&sB, g_sB);
    cudaGetSymbolAddress((void**)&relC, g_relC);
    cudaGetSymbolAddress((void**)&cnt, g_cnt);
    cudaGetSymbolAddress((void**)&off, g_off);
    cudaGetSymbolAddress((void**)&cur, g_cur);
    cudaGetSymbolAddress((void**)&csr_src, g_csr_src);
    cudaGetSymbolAddress((void**)&csr_et, g_csr_et);

    const dim3 gGemm1(cdiv(N, 128), 1);
    const dim3 gGemm2(cdiv(N, 128), 2);
    const int gNodeWarp = cdiv(N, 8);
    const int gEdge = cdiv(E, 256);

    // CSR build (once per launch; graph shared by both layers)
    cudaMemsetAsync(cnt, 0, N * sizeof(int));
    count_kernel<<<gEdge, 256>>>(dst, cnt, E);
    scan_kernel<<<1, 1024>>>(cnt, off, cur, N, E);
    fill_kernel<<<gEdge, 256>>>(src, dst, et, cur, csr_src, csr_et, E);

    // layer 0: h = leaky_relu(x @ l1W^T + b, 0.01)
    gemm_mma<<<gGemm1, 256>>>(x, l1W, l1b, h, nullptr, nullptr, nullptr, nullptr, nullptr,
                              N, IN_CH, F_BIASLEAKY);

    const float* Ws[2] = {W1, W2};
    const float* Wrs[2] = {Wr1, Wr2};
    const float* as[2] = {a1, a2};
    const float* Wress[2] = {Wres1, Wres2};
    const float* rels[2] = {rel1, rel2};

    for (int l = 0; l < 2; l++) {
        relc_kernel<<<1, 1024>>>(Wrs[l], as[l], rels[l], relC);
        // y=0: wx = h@W^T (+rowdot -> sA,sB); y=1: agg = h@Wres^T (residual)
        gemm_mma<<<gGemm2, 256>>>(h, Ws[l], nullptr, wx, Wress[l], agg, as[l], sA, sB,
                                  N, HID, F_ROWDOT);
        dst_fused_kernel<<<gNodeWarp, 256>>>(wx, agg, sA, sB, relC, off, csr_src, csr_et,
                                             h, N, l == 1 ? 1 : 0);
    }

    // final: out = leaky_relu(h @ l2W^T + l2b, 0.01)
    gemm_mma<<<gGemm1, 256>>>(h, l2W, l2b, (float*)d_out, nullptr, nullptr, nullptr, nullptr,
                              nullptr, N, HID, F_BIASLEAKY);
}